// round 15
// baseline (speedup 1.0000x reference)
#include <cuda_runtime.h>
#include <cuda_fp16.h>
#include <math.h>
#include <stdint.h>

// ---------------------------------------------------------------------------
// GCN_77893526880285 on GB300 (sm_103a)
// R15: aggregation restructured to 2 nodes per warp (16 lanes per node):
//      doubles per-warp MLP, halves warp count, widens per-lane loads.
//      GEMM path identical to R14 (GEMM1 measured 53.5us, kept at launch #4).
// ---------------------------------------------------------------------------

#define NMAX 100352
#define EMAX 1600000
#define NCHUNK_MAX 128
#define SCAN_BLOCK 1024

__device__ __half g_support1h[(size_t)NMAX * 128];  // 25.6 MB
__device__ float  g_support2[(size_t)NMAX * 64];    // 25.6 MB
__device__ float  g_W1r[256 * 128];
__device__ float  g_W2r[128 * 64];
__device__ int    g_counts[NMAX];
__device__ int    g_rowoff[NMAX + 1];
__device__ int    g_cursor[NMAX];
__device__ int2   g_edges[EMAX];
__device__ int    g_csum[NCHUNK_MAX];
__device__ int    g_coff[NCHUNK_MAX];

// ---------------------------- small helpers ---------------------------------

__device__ __forceinline__ uint32_t f2tf32(float v) {
    uint32_t u;
    asm("cvt.rna.tf32.f32 %0, %1;" : "=r"(u) : "f"(v));
    return u;
}

__global__ void dummy_kernel() {}

__global__ void round_weights_kernel(const float* __restrict__ W1, const float* __restrict__ W2,
                                     float* __restrict__ W1r, float* __restrict__ W2r,
                                     int n1, int n2) {
    int i = blockIdx.x * blockDim.x + threadIdx.x;
    if (i < n1) W1r[i] = __uint_as_float(f2tf32(W1[i]));
    else if (i < n1 + n2) W2r[i - n1] = __uint_as_float(f2tf32(W2[i - n1]));
}

// ---------------------------- CSR build ------------------------------------

__global__ void zero_counts_kernel(int* __restrict__ counts, int N) {
    int i = blockIdx.x * blockDim.x + threadIdx.x;
    if (i < N) counts[i] = 0;
}

__global__ void hist_kernel(const int* __restrict__ dst, int* __restrict__ counts, int E) {
    int i = blockIdx.x * blockDim.x + threadIdx.x;
    if (i < E) atomicAdd(&counts[dst[i]], 1);
}

__global__ void chunk_sum_kernel(const int* __restrict__ counts, int* __restrict__ csum, int N) {
    int i = blockIdx.x * SCAN_BLOCK + threadIdx.x;
    int v = (i < N) ? counts[i] : 0;
    #pragma unroll
    for (int o = 16; o; o >>= 1) v += __shfl_xor_sync(0xffffffffu, v, o);
    __shared__ int ws[32];
    if ((threadIdx.x & 31) == 0) ws[threadIdx.x >> 5] = v;
    __syncthreads();
    if (threadIdx.x < 32) {
        int x = ws[threadIdx.x];
        #pragma unroll
        for (int o = 16; o; o >>= 1) x += __shfl_xor_sync(0xffffffffu, x, o);
        if (threadIdx.x == 0) csum[blockIdx.x] = x;
    }
}

__global__ void chunk_scan_kernel(const int* __restrict__ csum, int* __restrict__ coff,
                                  int* __restrict__ rowoff, int nch, int N) {
    int tid = threadIdx.x;
    int v = (tid < nch) ? csum[tid] : 0;
    int lane = tid & 31, wid = tid >> 5;
    int x = v;
    #pragma unroll
    for (int o = 1; o < 32; o <<= 1) { int t = __shfl_up_sync(0xffffffffu, x, o); if (lane >= o) x += t; }
    __shared__ int ws[4];
    if (lane == 31) ws[wid] = x;
    __syncthreads();
    int base = 0;
    #pragma unroll
    for (int w = 0; w < 4; w++) if (w < wid) base += ws[w];
    int excl = base + x - v;
    if (tid < nch) coff[tid] = excl;
    if (tid == nch - 1) rowoff[N] = excl + v;
}

__global__ void scan_apply_kernel(const int* __restrict__ counts, const int* __restrict__ coff,
                                  int* __restrict__ rowoff, int* __restrict__ cursor, int N) {
    int tid = threadIdx.x, b = blockIdx.x;
    int i = b * SCAN_BLOCK + tid;
    int v = (i < N) ? counts[i] : 0;
    int lane = tid & 31, wid = tid >> 5;
    int x = v;
    #pragma unroll
    for (int o = 1; o < 32; o <<= 1) { int t = __shfl_up_sync(0xffffffffu, x, o); if (lane >= o) x += t; }
    __shared__ int ws[32];
    if (lane == 31) ws[wid] = x;
    __syncthreads();
    if (wid == 0) {
        int y = ws[lane];
        #pragma unroll
        for (int o = 1; o < 32; o <<= 1) { int t = __shfl_up_sync(0xffffffffu, y, o); if (lane >= o) y += t; }
        ws[lane] = y;
    }
    __syncthreads();
    int base = coff[b] + (wid ? ws[wid - 1] : 0);
    int excl = base + x - v;
    if (i < N) { rowoff[i] = excl; cursor[i] = excl; }
}

__global__ void scatter_kernel(const int* __restrict__ src, const int* __restrict__ dst,
                               const float* __restrict__ ew, int* __restrict__ cursor,
                               int2* __restrict__ edges, int E) {
    int i = blockIdx.x * blockDim.x + threadIdx.x;
    if (i < E) {
        int d = dst[i];
        int p = atomicAdd(&cursor[d], 1);
        edges[p] = make_int2(src[i], __float_as_int(ew[i]));
    }
}

// ---------------- TF32 GEMM, 3-stage cp.async (R14 version) ----------------

__device__ __forceinline__ void cp16(float* dst_smem, const float* src, int srcsz) {
    uint32_t d = (uint32_t)__cvta_generic_to_shared(dst_smem);
    asm volatile("cp.async.cg.shared.global [%0], [%1], 16, %2;\n"
                 :: "r"(d), "l"(src), "r"(srcsz));
}

__device__ __forceinline__ void mma_tf32(float c[4], const uint32_t a[4],
                                         uint32_t b0, uint32_t b1) {
    asm volatile("mma.sync.aligned.m16n8k8.row.col.f32.tf32.tf32.f32 "
                 "{%0,%1,%2,%3}, {%4,%5,%6,%7}, {%8,%9}, {%0,%1,%2,%3};\n"
                 : "+f"(c[0]), "+f"(c[1]), "+f"(c[2]), "+f"(c[3])
                 : "r"(a[0]), "r"(a[1]), "r"(a[2]), "r"(a[3]), "r"(b0), "r"(b1));
}

template<int BN, bool OUTH>
__global__ __launch_bounds__(256, 2)
void tf32_gemm_kernel(const float* __restrict__ A, const float* __restrict__ B,
                      void* __restrict__ Cv, int M, int K) {
    constexpr int BM = 128, BK = 32, S = 3;
    constexpr int ALD = 36;
    constexpr int BLD = BN + 8;
    constexpr int ASTG = BM * ALD;
    constexpr int BSTG = BK * BLD;
    constexpr int WN = BN / 2;
    constexpr int NT = WN / 8;
    extern __shared__ float sm[];
    float* As = sm;
    float* Bs = sm + S * ASTG;

    const int tid = threadIdx.x;
    const int warp = tid >> 5, lane = tid & 31;
    const int wm = warp >> 1, wn = warp & 1;
    const int lr = lane >> 2, lc = lane & 3;
    const int rowBase = blockIdx.x * BM;

    float c[2][NT][4];
    #pragma unroll
    for (int i = 0; i < 2; i++)
        #pragma unroll
        for (int j = 0; j < NT; j++)
            #pragma unroll
            for (int q = 0; q < 4; q++) c[i][j][q] = 0.f;

    const int ktiles = K / BK;

    auto fill = [&](int t, int stg) {
        int k0 = t * BK;
        #pragma unroll
        for (int it = 0; it < 4; it++) {
            int f = tid + it * 256;
            int row = f >> 3, k4 = f & 7;
            int gr = rowBase + row;
            const float* srcp = A + (size_t)(gr < M ? gr : 0) * K + k0 + k4 * 4;
            cp16(As + stg * ASTG + row * ALD + k4 * 4, srcp, gr < M ? 16 : 0);
        }
        constexpr int BCH = (BK * BN / 4) / 256;
        #pragma unroll
        for (int it = 0; it < BCH; it++) {
            int f = tid + it * 256;
            int krow = f / (BN / 4), nc = f % (BN / 4);
            cp16(Bs + stg * BSTG + krow * BLD + nc * 4,
                 B + (size_t)(k0 + krow) * BN + nc * 4, 16);
        }
        asm volatile("cp.async.commit_group;\n");
    };

    fill(0, 0);
    if (1 < ktiles) fill(1, 1);

    for (int t = 0; t < ktiles; t++) {
        if (t < ktiles - 1) asm volatile("cp.async.wait_group 1;\n");
        else                asm volatile("cp.async.wait_group 0;\n");
        __syncthreads();
        if (t + 2 < ktiles) fill(t + 2, (t + 2) % S);

        const float* Ab = As + (t % S) * ASTG;
        const float* Bb = Bs + (t % S) * BSTG;

        uint32_t a[2][2][4];
        #pragma unroll
        for (int mt = 0; mt < 2; mt++) {
            const float* ap = Ab + (wm * 32 + mt * 16 + lr) * ALD + lc;
            a[0][mt][0] = f2tf32(ap[0]);
            a[0][mt][2] = f2tf32(ap[4]);
            a[0][mt][1] = f2tf32(ap[8 * ALD]);
            a[0][mt][3] = f2tf32(ap[8 * ALD + 4]);
        }

        #pragma unroll
        for (int g = 0; g < BK / 8; g++) {
            const int cb = g & 1, nb = cb ^ 1;
            uint32_t b[NT][2];
            #pragma unroll
            for (int nt = 0; nt < NT; nt++) {
                const float* bp = Bb + (g * 8 + lc) * BLD + wn * WN + nt * 8 + lr;
                b[nt][0] = __float_as_uint(bp[0]);
                b[nt][1] = __float_as_uint(bp[4 * BLD]);
            }
            if (g + 1 < BK / 8) {
                #pragma unroll
                for (int mt = 0; mt < 2; mt++) {
                    const float* ap = Ab + (wm * 32 + mt * 16 + lr) * ALD + (g + 1) * 8 + lc;
                    a[nb][mt][0] = f2tf32(ap[0]);
                    a[nb][mt][2] = f2tf32(ap[4]);
                    a[nb][mt][1] = f2tf32(ap[8 * ALD]);
                    a[nb][mt][3] = f2tf32(ap[8 * ALD + 4]);
                }
            }
            #pragma unroll
            for (int nt = 0; nt < NT; nt++)
                #pragma unroll
                for (int mt = 0; mt < 2; mt++)
                    mma_tf32(c[mt][nt], a[cb][mt], b[nt][0], b[nt][1]);
        }
        __syncthreads();
    }

    #pragma unroll
    for (int mt = 0; mt < 2; mt++) {
        int r0 = rowBase + wm * 32 + mt * 16 + lr;
        #pragma unroll
        for (int nt = 0; nt < NT; nt++) {
            int col = wn * WN + nt * 8 + 2 * lc;
            if (OUTH) {
                __half* C = (__half*)Cv;
                if (r0 < M)
                    *reinterpret_cast<__half2*>(&C[(size_t)r0 * BN + col]) =
                        __floats2half2_rn(c[mt][nt][0], c[mt][nt][1]);
                if (r0 + 8 < M)
                    *reinterpret_cast<__half2*>(&C[(size_t)(r0 + 8) * BN + col]) =
                        __floats2half2_rn(c[mt][nt][2], c[mt][nt][3]);
            } else {
                float* C = (float*)Cv;
                if (r0 < M)
                    *reinterpret_cast<float2*>(&C[(size_t)r0 * BN + col]) =
                        make_float2(c[mt][nt][0], c[mt][nt][1]);
                if (r0 + 8 < M)
                    *reinterpret_cast<float2*>(&C[(size_t)(r0 + 8) * BN + col]) =
                        make_float2(c[mt][nt][2], c[mt][nt][3]);
            }
        }
    }
}

// --------- Aggregation: 2 nodes per warp, 16 lanes per node, 4x unroll -------

// layer 1: support fp16 [N,128] = 256B/row; lane owns 8 feats (uint4 = 16B).
__global__ __launch_bounds__(128)
void agg1_kernel(const __half* __restrict__ support, const int* __restrict__ rowoff,
                 const int2* __restrict__ edges,
                 const float* __restrict__ bias, float* __restrict__ out, int N) {
    int gw = (blockIdx.x * blockDim.x + threadIdx.x) >> 5;
    int lane = threadIdx.x & 31;
    int half = lane >> 4, hl = lane & 15;
    int node = gw * 2 + half;
    bool valid = node < N;
    int nodec = valid ? node : (N - 1);
    int s = rowoff[nodec], e = rowoff[nodec + 1];
    const uint4* base = reinterpret_cast<const uint4*>(support);   // 16 uint4/row
    float4 a0 = make_float4(0.f, 0.f, 0.f, 0.f);
    float4 a1 = make_float4(0.f, 0.f, 0.f, 0.f);
    float4 b0 = make_float4(0.f, 0.f, 0.f, 0.f);
    float4 b1 = make_float4(0.f, 0.f, 0.f, 0.f);
    int j = s;
    for (; j + 4 <= e; j += 4) {
        int2 ee[4];
        #pragma unroll
        for (int q = 0; q < 4; q++) ee[q] = __ldg(&edges[j + q]);
        uint4 v[4];
        #pragma unroll
        for (int q = 0; q < 4; q++) v[q] = __ldg(&base[(size_t)ee[q].x * 16 + hl]);
        #pragma unroll
        for (int q = 0; q < 4; q++) {
            float w = __int_as_float(ee[q].y);
            float2 f0 = __half22float2(*reinterpret_cast<__half2*>(&v[q].x));
            float2 f1 = __half22float2(*reinterpret_cast<__half2*>(&v[q].y));
            float2 f2 = __half22float2(*reinterpret_cast<__half2*>(&v[q].z));
            float2 f3 = __half22float2(*reinterpret_cast<__half2*>(&v[q].w));
            float4* pa = (q & 1) ? &b0 : &a0;
            float4* pb = (q & 1) ? &b1 : &a1;
            pa->x = fmaf(w, f0.x, pa->x); pa->y = fmaf(w, f0.y, pa->y);
            pa->z = fmaf(w, f1.x, pa->z); pa->w = fmaf(w, f1.y, pa->w);
            pb->x = fmaf(w, f2.x, pb->x); pb->y = fmaf(w, f2.y, pb->y);
            pb->z = fmaf(w, f3.x, pb->z); pb->w = fmaf(w, f3.y, pb->w);
        }
    }
    for (; j < e; j++) {
        int2 e0 = __ldg(&edges[j]);
        float w = __int_as_float(e0.y);
        uint4 v = __ldg(&base[(size_t)e0.x * 16 + hl]);
        float2 f0 = __half22float2(*reinterpret_cast<__half2*>(&v.x));
        float2 f1 = __half22float2(*reinterpret_cast<__half2*>(&v.y));
        float2 f2 = __half22float2(*reinterpret_cast<__half2*>(&v.z));
        float2 f3 = __half22float2(*reinterpret_cast<__half2*>(&v.w));
        a0.x = fmaf(w, f0.x, a0.x); a0.y = fmaf(w, f0.y, a0.y);
        a0.z = fmaf(w, f1.x, a0.z); a0.w = fmaf(w, f1.y, a0.w);
        a1.x = fmaf(w, f2.x, a1.x); a1.y = fmaf(w, f2.y, a1.y);
        a1.z = fmaf(w, f3.x, a1.z); a1.w = fmaf(w, f3.y, a1.w);
    }
    float4 bb0 = *reinterpret_cast<const float4*>(bias + hl * 8);
    float4 bb1 = *reinterpret_cast<const float4*>(bias + hl * 8 + 4);
    if (valid) {
        float4 r0, r1;
        r0.x = fmaxf(a0.x + b0.x + bb0.x, 0.f);
        r0.y = fmaxf(a0.y + b0.y + bb0.y, 0.f);
        r0.z = fmaxf(a0.z + b0.z + bb0.z, 0.f);
        r0.w = fmaxf(a0.w + b0.w + bb0.w, 0.f);
        r1.x = fmaxf(a1.x + b1.x + bb1.x, 0.f);
        r1.y = fmaxf(a1.y + b1.y + bb1.y, 0.f);
        r1.z = fmaxf(a1.z + b1.z + bb1.z, 0.f);
        r1.w = fmaxf(a1.w + b1.w + bb1.w, 0.f);
        float* op = out + (size_t)node * 128 + hl * 8;
        *reinterpret_cast<float4*>(op) = r0;
        *reinterpret_cast<float4*>(op + 4) = r1;
    }
}

// layer 2: support fp32 [N,64] = 256B/row; lane owns 4 feats (float4 = 16B).
__global__ __launch_bounds__(128)
void agg2_kernel(const float* __restrict__ support, const int* __restrict__ rowoff,
                 const int2* __restrict__ edges,
                 const float* __restrict__ bias, float* __restrict__ out, int N) {
    int gw = (blockIdx.x * blockDim.x + threadIdx.x) >> 5;
    int lane = threadIdx.x & 31;
    int half = lane >> 4, hl = lane & 15;
    int node = gw * 2 + half;
    bool valid = node < N;
    int nodec = valid ? node : (N - 1);
    int s = rowoff[nodec], e = rowoff[nodec + 1];
    const float4* base = reinterpret_cast<const float4*>(support);  // 16 float4/row
    float4 a0 = make_float4(0.f, 0.f, 0.f, 0.f);
    float4 b0 = make_float4(0.f, 0.f, 0.f, 0.f);
    int j = s;
    for (; j + 4 <= e; j += 4) {
        int2 ee[4];
        #pragma unroll
        for (int q = 0; q < 4; q++) ee[q] = __ldg(&edges[j + q]);
        float4 v[4];
        #pragma unroll
        for (int q = 0; q < 4; q++) v[q] = __ldg(&base[(size_t)ee[q].x * 16 + hl]);
        #pragma unroll
        for (int q = 0; q < 4; q++) {
            float w = __int_as_float(ee[q].y);
            float4* ac = (q & 1) ? &b0 : &a0;
            ac->x = fmaf(w, v[q].x, ac->x); ac->y = fmaf(w, v[q].y, ac->y);
            ac->z = fmaf(w, v[q].z, ac->z); ac->w = fmaf(w, v[q].w, ac->w);
        }
    }
    for (; j < e; j++) {
        int2 e0 = __ldg(&edges[j]);
        float w = __int_as_float(e0.y);
        float4 v = __ldg(&base[(size_t)e0.x * 16 + hl]);
        a0.x = fmaf(w, v.x, a0.x); a0.y = fmaf(w, v.y, a0.y);
        a0.z = fmaf(w, v.z, a0.z); a0.w = fmaf(w, v.w, a0.w);
    }
    float4 bb = *reinterpret_cast<const float4*>(bias + hl * 4);
    float x0 = a0.x + b0.x + bb.x;
    float x1 = a0.y + b0.y + bb.y;
    float x2 = a0.z + b0.z + bb.z;
    float x3 = a0.w + b0.w + bb.w;
    // log_softmax over 64 values spread across 16 lanes (4 each)
    float m = fmaxf(fmaxf(x0, x1), fmaxf(x2, x3));
    #pragma unroll
    for (int o = 8; o; o >>= 1) m = fmaxf(m, __shfl_xor_sync(0xffffffffu, m, o));
    float es = __expf(x0 - m) + __expf(x1 - m) + __expf(x2 - m) + __expf(x3 - m);
    #pragma unroll
    for (int o = 8; o; o >>= 1) es += __shfl_xor_sync(0xffffffffu, es, o);
    float ls = m + __logf(es);
    if (valid) {
        *reinterpret_cast<float4*>(out + (size_t)node * 64 + hl * 4) =
            make_float4(x0 - ls, x1 - ls, x2 - ls, x3 - ls);
    }
}

// ---------------------------- launch ----------------------------------------

extern "C" void kernel_launch(void* const* d_in, const int* in_sizes, int n_in,
                              void* d_out, int out_size) {
    const float* feature = (const float*)d_in[0];
    const int*   src     = (const int*)d_in[1];
    const int*   dst     = (const int*)d_in[2];
    const float* ew      = (const float*)d_in[3];
    const float* W1      = (const float*)d_in[4];
    const float* b1      = (const float*)d_in[5];
    const float* W2      = (const float*)d_in[6];
    const float* b2      = (const float*)d_in[7];
    float* out = (float*)d_out;

    const int E    = in_sizes[1];
    const int H    = in_sizes[5];            // 128
    const int F_IN = in_sizes[4] / H;        // 256
    const int N    = in_sizes[0] / F_IN;     // 100000

    float* x1 = out;                          // [N, 128]
    float* x2 = out + (size_t)N * 128;        // [N, 64]

    void *p_sup1h, *p_sup2, *p_counts, *p_rowoff, *p_cursor, *p_edges, *p_csum, *p_coff;
    void *p_w1r, *p_w2r;
    cudaGetSymbolAddress(&p_sup1h,  g_support1h);
    cudaGetSymbolAddress(&p_sup2,   g_support2);
    cudaGetSymbolAddress(&p_counts, g_counts);
    cudaGetSymbolAddress(&p_rowoff, g_rowoff);
    cudaGetSymbolAddress(&p_cursor, g_cursor);
    cudaGetSymbolAddress(&p_edges,  g_edges);
    cudaGetSymbolAddress(&p_csum,   g_csum);
    cudaGetSymbolAddress(&p_coff,   g_coff);
    cudaGetSymbolAddress(&p_w1r,    g_W1r);
    cudaGetSymbolAddress(&p_w2r,    g_W2r);

    constexpr int SMEM1 = 3 * (128 * 36 + 32 * 136) * 4;   // 107520 B
    constexpr int SMEM2 = 3 * (128 * 36 + 32 * 72) * 4;    //  82944 B
    cudaFuncSetAttribute((const void*)tf32_gemm_kernel<128, true>,
                         cudaFuncAttributeMaxDynamicSharedMemorySize, SMEM1);
    cudaFuncSetAttribute((const void*)tf32_gemm_kernel<64, false>,
                         cudaFuncAttributeMaxDynamicSharedMemorySize, SMEM2);

    static cudaStream_t s_side = nullptr;
    static cudaEvent_t ev_fork = nullptr, ev_join = nullptr;
    if (s_side == nullptr) {
        cudaStreamCreateWithFlags(&s_side, cudaStreamNonBlocking);
        cudaEventCreateWithFlags(&ev_fork, cudaEventDisableTiming);
        cudaEventCreateWithFlags(&ev_join, cudaEventDisableTiming);
    }

    const int nch = (N + SCAN_BLOCK - 1) / SCAN_BLOCK;
    const int n1 = F_IN * H, n2 = H * 64;

    // kernel launch #1: weight rounding
    round_weights_kernel<<<(n1 + n2 + 255) / 256, 256>>>(W1, W2, (float*)p_w1r, (float*)p_w2r,
                                                         n1, n2);

    cudaEventRecord(ev_fork, 0);
    cudaStreamWaitEvent(s_side, ev_fork, 0);

    // kernel launches #2, #3: padding so GEMM1 sits in the ncu window
    dummy_kernel<<<1, 32>>>();
    dummy_kernel<<<1, 32>>>();

    // kernel launch #4: GEMM1
    tf32_gemm_kernel<128, true><<<(N + 127) / 128, 256, SMEM1>>>(feature, (float*)p_w1r,
                                                                 p_sup1h, N, F_IN);

    // side-stream CSR build (concurrent with GEMM1)
    zero_counts_kernel<<<(N + 255) / 256, 256, 0, s_side>>>((int*)p_counts, N);
    hist_kernel<<<(E + 255) / 256, 256, 0, s_side>>>(dst, (int*)p_counts, E);
    chunk_sum_kernel<<<nch, SCAN_BLOCK, 0, s_side>>>((int*)p_counts, (int*)p_csum, N);
    chunk_scan_kernel<<<1, 128, 0, s_side>>>((int*)p_csum, (int*)p_coff, (int*)p_rowoff, nch, N);
    scan_apply_kernel<<<nch, SCAN_BLOCK, 0, s_side>>>((int*)p_counts, (int*)p_coff,
                                                      (int*)p_rowoff, (int*)p_cursor, N);
    scatter_kernel<<<(E + 255) / 256, 256, 0, s_side>>>(src, dst, ew, (int*)p_cursor,
                                                        (int2*)p_edges, E);

    cudaEventRecord(ev_join, s_side);
    cudaStreamWaitEvent(0, ev_join, 0);

    {
        long long warps = (N + 1) / 2;                 // 2 nodes per warp
        long long threads = warps * 32;
        agg1_kernel<<<(unsigned)((threads + 127) / 128), 128>>>(
            (const __half*)p_sup1h, (int*)p_rowoff, (int2*)p_edges, b1, x1, N);
    }

    tf32_gemm_kernel<64, false><<<(N + 127) / 128, 256, SMEM2>>>(x1, (float*)p_w2r,
                                                                 p_sup2, N, 128);

    {
        long long warps = (N + 1) / 2;
        long long threads = warps * 32;
        agg2_kernel<<<(unsigned)((threads + 127) / 128), 128>>>(
            (float*)p_sup2, (int*)p_rowoff, (int2*)p_edges, b2, x2, N);
    }
}

// round 16
// speedup vs baseline: 1.0221x; 1.0221x over previous
#include <cuda_runtime.h>
#include <cuda_fp16.h>
#include <math.h>
#include <stdint.h>

// ---------------------------------------------------------------------------
// GCN_77893526880285 on GB300 (sm_103a)
// R16: GEMMs moved from tf32 m16n8k8 to fp16 m16n8k16 (half the MMA
//      instructions, 2x per-instruction rate, half the B LDS traffic).
//      Weights pre-transposed+converted to fp16 [n][k]; A fp32 in smem,
//      cvt'd to half2 on register load. Aggs = proven R14 versions.
//      GEMM1 kept at launch #4 for the ncu window.
// ---------------------------------------------------------------------------

#define NMAX 100352
#define EMAX 1600000
#define NCHUNK_MAX 128
#define SCAN_BLOCK 1024

__device__ __half g_support1h[(size_t)NMAX * 128];  // 25.6 MB
__device__ float  g_support2[(size_t)NMAX * 64];    // 25.6 MB
__device__ __half g_B1t[128 * 256];                 // W1^T fp16 [n=128][k=256]
__device__ __half g_B2t[64 * 128];                  // W2^T fp16 [n=64][k=128]
__device__ int    g_counts[NMAX];
__device__ int    g_rowoff[NMAX + 1];
__device__ int    g_cursor[NMAX];
__device__ int2   g_edges[EMAX];
__device__ int    g_csum[NCHUNK_MAX];
__device__ int    g_coff[NCHUNK_MAX];

// ---------------------------- small helpers ---------------------------------

__global__ void dummy_kernel() {}

// W1 [K=256][N=128] -> B1t [128][256] fp16 ; W2 [128][64] -> B2t [64][128]
__global__ void prep_w_kernel(const float* __restrict__ W1, const float* __restrict__ W2,
                              __half* __restrict__ B1t, __half* __restrict__ B2t) {
    int i = blockIdx.x * blockDim.x + threadIdx.x;
    if (i < 128 * 256) {
        int n = i / 256, k = i % 256;
        B1t[i] = __float2half_rn(W1[k * 128 + n]);
    } else if (i < 128 * 256 + 64 * 128) {
        int j = i - 128 * 256;
        int n = j / 128, k = j % 128;
        B2t[j] = __float2half_rn(W2[k * 64 + n]);
    }
}

// ---------------------------- CSR build ------------------------------------

__global__ void zero_counts_kernel(int* __restrict__ counts, int N) {
    int i = blockIdx.x * blockDim.x + threadIdx.x;
    if (i < N) counts[i] = 0;
}

__global__ void hist_kernel(const int* __restrict__ dst, int* __restrict__ counts, int E) {
    int i = blockIdx.x * blockDim.x + threadIdx.x;
    if (i < E) atomicAdd(&counts[dst[i]], 1);
}

__global__ void chunk_sum_kernel(const int* __restrict__ counts, int* __restrict__ csum, int N) {
    int i = blockIdx.x * SCAN_BLOCK + threadIdx.x;
    int v = (i < N) ? counts[i] : 0;
    #pragma unroll
    for (int o = 16; o; o >>= 1) v += __shfl_xor_sync(0xffffffffu, v, o);
    __shared__ int ws[32];
    if ((threadIdx.x & 31) == 0) ws[threadIdx.x >> 5] = v;
    __syncthreads();
    if (threadIdx.x < 32) {
        int x = ws[threadIdx.x];
        #pragma unroll
        for (int o = 16; o; o >>= 1) x += __shfl_xor_sync(0xffffffffu, x, o);
        if (threadIdx.x == 0) csum[blockIdx.x] = x;
    }
}

__global__ void chunk_scan_kernel(const int* __restrict__ csum, int* __restrict__ coff,
                                  int* __restrict__ rowoff, int nch, int N) {
    int tid = threadIdx.x;
    int v = (tid < nch) ? csum[tid] : 0;
    int lane = tid & 31, wid = tid >> 5;
    int x = v;
    #pragma unroll
    for (int o = 1; o < 32; o <<= 1) { int t = __shfl_up_sync(0xffffffffu, x, o); if (lane >= o) x += t; }
    __shared__ int ws[4];
    if (lane == 31) ws[wid] = x;
    __syncthreads();
    int base = 0;
    #pragma unroll
    for (int w = 0; w < 4; w++) if (w < wid) base += ws[w];
    int excl = base + x - v;
    if (tid < nch) coff[tid] = excl;
    if (tid == nch - 1) rowoff[N] = excl + v;
}

__global__ void scan_apply_kernel(const int* __restrict__ counts, const int* __restrict__ coff,
                                  int* __restrict__ rowoff, int* __restrict__ cursor, int N) {
    int tid = threadIdx.x, b = blockIdx.x;
    int i = b * SCAN_BLOCK + tid;
    int v = (i < N) ? counts[i] : 0;
    int lane = tid & 31, wid = tid >> 5;
    int x = v;
    #pragma unroll
    for (int o = 1; o < 32; o <<= 1) { int t = __shfl_up_sync(0xffffffffu, x, o); if (lane >= o) x += t; }
    __shared__ int ws[32];
    if (lane == 31) ws[wid] = x;
    __syncthreads();
    if (wid == 0) {
        int y = ws[lane];
        #pragma unroll
        for (int o = 1; o < 32; o <<= 1) { int t = __shfl_up_sync(0xffffffffu, y, o); if (lane >= o) y += t; }
        ws[lane] = y;
    }
    __syncthreads();
    int base = coff[b] + (wid ? ws[wid - 1] : 0);
    int excl = base + x - v;
    if (i < N) { rowoff[i] = excl; cursor[i] = excl; }
}

__global__ void scatter_kernel(const int* __restrict__ src, const int* __restrict__ dst,
                               const float* __restrict__ ew, int* __restrict__ cursor,
                               int2* __restrict__ edges, int E) {
    int i = blockIdx.x * blockDim.x + threadIdx.x;
    if (i < E) {
        int d = dst[i];
        int p = atomicAdd(&cursor[d], 1);
        edges[p] = make_int2(src[i], __float_as_int(ew[i]));
    }
}

// ---------------- FP16 GEMM (m16n8k16), 3-stage cp.async --------------------
// C[M,BN] = A[M,K] @ W where Bt[n][k] fp16 pre-transposed.
// A fp32 in smem (pad 36), converted to half2 in registers.
// B fp16 in smem [n][k] with 40-half pitch (conflict-free, cp.async-filled).

__device__ __forceinline__ void cp16(void* dst_smem, const void* src, int srcsz) {
    uint32_t d = (uint32_t)__cvta_generic_to_shared(dst_smem);
    asm volatile("cp.async.cg.shared.global [%0], [%1], 16, %2;\n"
                 :: "r"(d), "l"(src), "r"(srcsz));
}

__device__ __forceinline__ uint32_t packh2(float x, float y) {
    __half2 h = __floats2half2_rn(x, y);
    return *reinterpret_cast<uint32_t*>(&h);
}

__device__ __forceinline__ void mma_f16(float c[4], const uint32_t a[4],
                                        uint32_t b0, uint32_t b1) {
    asm volatile("mma.sync.aligned.m16n8k16.row.col.f32.f16.f16.f32 "
                 "{%0,%1,%2,%3}, {%4,%5,%6,%7}, {%8,%9}, {%0,%1,%2,%3};\n"
                 : "+f"(c[0]), "+f"(c[1]), "+f"(c[2]), "+f"(c[3])
                 : "r"(a[0]), "r"(a[1]), "r"(a[2]), "r"(a[3]), "r"(b0), "r"(b1));
}

template<int BN, bool OUTH>
__global__ __launch_bounds__(256, 2)
void f16_gemm_kernel(const float* __restrict__ A, const __half* __restrict__ Bt,
                     void* __restrict__ Cv, int M, int K) {
    constexpr int BM = 128, BK = 32, S = 3;
    constexpr int ALD = 36;                   // floats
    constexpr int BKH = 40;                   // halves pitch per n-row
    constexpr int ASTG = BM * ALD;            // floats
    constexpr int BSTG = BN * BKH;            // halves
    constexpr int WN = BN / 2;
    constexpr int NT = WN / 8;
    extern __shared__ float sm[];
    float* As = sm;                           // [S][BM][ALD] fp32
    __half* Bs = reinterpret_cast<__half*>(sm + S * ASTG);  // [S][BN][BKH] fp16

    const int tid = threadIdx.x;
    const int warp = tid >> 5, lane = tid & 31;
    const int wm = warp >> 1, wn = warp & 1;
    const int lr = lane >> 2, lc = lane & 3;
    const int rowBase = blockIdx.x * BM;

    float c[2][NT][4];
    #pragma unroll
    for (int i = 0; i < 2; i++)
        #pragma unroll
        for (int j = 0; j < NT; j++)
            #pragma unroll
            for (int q = 0; q < 4; q++) c[i][j][q] = 0.f;

    const int ktiles = K / BK;

    auto fill = [&](int t, int stg) {
        int k0 = t * BK;
        #pragma unroll
        for (int it = 0; it < 4; it++) {                 // A: 1024 16B chunks
            int f = tid + it * 256;
            int row = f >> 3, k4 = f & 7;
            int gr = rowBase + row;
            const float* srcp = A + (size_t)(gr < M ? gr : 0) * K + k0 + k4 * 4;
            cp16(As + stg * ASTG + row * ALD + k4 * 4, srcp, gr < M ? 16 : 0);
        }
        constexpr int BCH = (BN * BK / 8) / 256;         // 2 (BN=128) / 1 (BN=64)
        #pragma unroll
        for (int it = 0; it < BCH; it++) {               // B: 16B = 8 halves
            int f = tid + it * 256;
            int n = f / (BK / 8), kc = f % (BK / 8);
            cp16(Bs + stg * BSTG + n * BKH + kc * 8,
                 Bt + (size_t)n * K + k0 + kc * 8, 16);
        }
        asm volatile("cp.async.commit_group;\n");
    };

    fill(0, 0);
    if (1 < ktiles) fill(1, 1);

    for (int t = 0; t < ktiles; t++) {
        if (t < ktiles - 1) asm volatile("cp.async.wait_group 1;\n");
        else                asm volatile("cp.async.wait_group 0;\n");
        __syncthreads();
        if (t + 2 < ktiles) fill(t + 2, (t + 2) % S);

        const float* Ab = As + (t % S) * ASTG;
        const __half* Bb = Bs + (t % S) * BSTG;

        #pragma unroll
        for (int g = 0; g < BK / 16; g++) {              // 2 k16-steps
            uint32_t a[2][4];
            #pragma unroll
            for (int mt = 0; mt < 2; mt++) {
                const float* ap = Ab + (wm * 32 + mt * 16 + lr) * ALD + g * 16 + 2 * lc;
                float2 v0 = *reinterpret_cast<const float2*>(ap);
                float2 v1 = *reinterpret_cast<const float2*>(ap + 8);
                float2 w0 = *reinterpret_cast<const float2*>(ap + 8 * ALD);
                float2 w1 = *reinterpret_cast<const float2*>(ap + 8 * ALD + 8);
                a[mt][0] = packh2(v0.x, v0.y);
                a[mt][1] = packh2(w0.x, w0.y);
                a[mt][2] = packh2(v1.x, v1.y);
                a[mt][3] = packh2(w1.x, w1.y);
            }
            #pragma unroll
            for (int nt = 0; nt < NT; nt++) {
                const __half* bp = Bb + (wn * WN + nt * 8 + lr) * BKH + g * 16 + 2 * lc;
                uint32_t b0 = *reinterpret_cast<const uint32_t*>(bp);
                uint32_t b1 = *reinterpret_cast<const uint32_t*>(bp + 8);
                #pragma unroll
                for (int mt = 0; mt < 2; mt++)
                    mma_f16(c[mt][nt], a[mt], b0, b1);
            }
        }
        __syncthreads();
    }

    #pragma unroll
    for (int mt = 0; mt < 2; mt++) {
        int r0 = rowBase + wm * 32 + mt * 16 + lr;
        #pragma unroll
        for (int nt = 0; nt < NT; nt++) {
            int col = wn * WN + nt * 8 + 2 * lc;
            if (OUTH) {
                __half* C = (__half*)Cv;
                if (r0 < M)
                    *reinterpret_cast<__half2*>(&C[(size_t)r0 * BN + col]) =
                        __floats2half2_rn(c[mt][nt][0], c[mt][nt][1]);
                if (r0 + 8 < M)
                    *reinterpret_cast<__half2*>(&C[(size_t)(r0 + 8) * BN + col]) =
                        __floats2half2_rn(c[mt][nt][2], c[mt][nt][3]);
            } else {
                float* C = (float*)Cv;
                if (r0 < M)
                    *reinterpret_cast<float2*>(&C[(size_t)r0 * BN + col]) =
                        make_float2(c[mt][nt][0], c[mt][nt][1]);
                if (r0 + 8 < M)
                    *reinterpret_cast<float2*>(&C[(size_t)(r0 + 8) * BN + col]) =
                        make_float2(c[mt][nt][2], c[mt][nt][3]);
            }
        }
    }
}

// ------------------- Aggregation (warp per node, 8x unrolled) ----------------

__global__ __launch_bounds__(128)
void agg1_kernel(const __half* __restrict__ support, const int* __restrict__ rowoff,
                 const int2* __restrict__ edges,
                 const float* __restrict__ bias, float* __restrict__ out, int N) {
    int gw = (blockIdx.x * blockDim.x + threadIdx.x) >> 5;
    int lane = threadIdx.x & 31;
    if (gw >= N) return;
    int s = rowoff[gw], e = rowoff[gw + 1];
    const uint2* base = reinterpret_cast<const uint2*>(support);
    float4 acc0 = make_float4(0.f, 0.f, 0.f, 0.f);
    float4 acc1 = make_float4(0.f, 0.f, 0.f, 0.f);
    int j = s;
    for (; j + 8 <= e; j += 8) {
        int2 ee[8];
        #pragma unroll
        for (int q = 0; q < 8; q++) ee[q] = __ldg(&edges[j + q]);
        uint2 v[8];
        #pragma unroll
        for (int q = 0; q < 8; q++) v[q] = __ldg(&base[(size_t)ee[q].x * 32 + lane]);
        #pragma unroll
        for (int q = 0; q < 8; q++) {
            float w = __int_as_float(ee[q].y);
            float2 f0 = __half22float2(*reinterpret_cast<__half2*>(&v[q].x));
            float2 f1 = __half22float2(*reinterpret_cast<__half2*>(&v[q].y));
            float4* ac = (q & 1) ? &acc1 : &acc0;
            ac->x = fmaf(w, f0.x, ac->x); ac->y = fmaf(w, f0.y, ac->y);
            ac->z = fmaf(w, f1.x, ac->z); ac->w = fmaf(w, f1.y, ac->w);
        }
    }
    for (; j < e; j++) {
        int2 e0 = __ldg(&edges[j]);
        float w = __int_as_float(e0.y);
        uint2 v = __ldg(&base[(size_t)e0.x * 32 + lane]);
        float2 f0 = __half22float2(*reinterpret_cast<__half2*>(&v.x));
        float2 f1 = __half22float2(*reinterpret_cast<__half2*>(&v.y));
        acc0.x = fmaf(w, f0.x, acc0.x); acc0.y = fmaf(w, f0.y, acc0.y);
        acc0.z = fmaf(w, f1.x, acc0.z); acc0.w = fmaf(w, f1.y, acc0.w);
    }
    float4 bb = *(reinterpret_cast<const float4*>(bias) + lane);
    float4 r;
    r.x = fmaxf(acc0.x + acc1.x + bb.x, 0.f);
    r.y = fmaxf(acc0.y + acc1.y + bb.y, 0.f);
    r.z = fmaxf(acc0.z + acc1.z + bb.z, 0.f);
    r.w = fmaxf(acc0.w + acc1.w + bb.w, 0.f);
    *(reinterpret_cast<float4*>(&out[(size_t)gw * 128]) + lane) = r;
}

__global__ __launch_bounds__(128)
void agg2_kernel(const float* __restrict__ support, const int* __restrict__ rowoff,
                 const int2* __restrict__ edges,
                 const float* __restrict__ bias, float* __restrict__ out, int N) {
    int gw = (blockIdx.x * blockDim.x + threadIdx.x) >> 5;
    int lane = threadIdx.x & 31;
    if (gw >= N) return;
    int s = rowoff[gw], e = rowoff[gw + 1];
    float2 acc0 = make_float2(0.f, 0.f), acc1 = make_float2(0.f, 0.f);
    int j = s;
    for (; j + 8 <= e; j += 8) {
        int2 ee[8];
        #pragma unroll
        for (int q = 0; q < 8; q++) ee[q] = __ldg(&edges[j + q]);
        float2 v[8];
        #pragma unroll
        for (int q = 0; q < 8; q++)
            v[q] = *(reinterpret_cast<const float2*>(&support[(size_t)ee[q].x * 64]) + lane);
        #pragma unroll
        for (int q = 0; q < 8; q++) {
            float w = __int_as_float(ee[q].y);
            float2* ac = (q & 1) ? &acc1 : &acc0;
            ac->x = fmaf(w, v[q].x, ac->x); ac->y = fmaf(w, v[q].y, ac->y);
        }
    }
    for (; j < e; j++) {
        int2 e0 = __ldg(&edges[j]);
        float w = __int_as_float(e0.y);
        float2 v = *(reinterpret_cast<const float2*>(&support[(size_t)e0.x * 64]) + lane);
        acc0.x = fmaf(w, v.x, acc0.x); acc0.y = fmaf(w, v.y, acc0.y);
    }
    float2 bb = *(reinterpret_cast<const float2*>(bias) + lane);
    float ax = acc0.x + acc1.x + bb.x;
    float ay = acc0.y + acc1.y + bb.y;
    float m = fmaxf(ax, ay);
    #pragma unroll
    for (int o = 16; o; o >>= 1) m = fmaxf(m, __shfl_xor_sync(0xffffffffu, m, o));
    float es = __expf(ax - m) + __expf(ay - m);
    #pragma unroll
    for (int o = 16; o; o >>= 1) es += __shfl_xor_sync(0xffffffffu, es, o);
    float ls = m + __logf(es);
    *(reinterpret_cast<float2*>(&out[(size_t)gw * 64]) + lane) = make_float2(ax - ls, ay - ls);
}

// ---------------------------- launch ----------------------------------------

extern "C" void kernel_launch(void* const* d_in, const int* in_sizes, int n_in,
                              void* d_out, int out_size) {
    const float* feature = (const float*)d_in[0];
    const int*   src     = (const int*)d_in[1];
    const int*   dst     = (const int*)d_in[2];
    const float* ew      = (const float*)d_in[3];
    const float* W1      = (const float*)d_in[4];
    const float* b1      = (const float*)d_in[5];
    const float* W2      = (const float*)d_in[6];
    const float* b2      = (const float*)d_in[7];
    float* out = (float*)d_out;

    const int E    = in_sizes[1];
    const int H    = in_sizes[5];            // 128
    const int F_IN = in_sizes[4] / H;        // 256
    const int N    = in_sizes[0] / F_IN;     // 100000

    float* x1 = out;                          // [N, 128]
    float* x2 = out + (size_t)N * 128;        // [N, 64]

    void *p_sup1h, *p_sup2, *p_counts, *p_rowoff, *p_cursor, *p_edges, *p_csum, *p_coff;
    void *p_b1t, *p_b2t;
    cudaGetSymbolAddress(&p_sup1h,  g_support1h);
    cudaGetSymbolAddress(&p_sup2,   g_support2);
    cudaGetSymbolAddress(&p_counts, g_counts);
    cudaGetSymbolAddress(&p_rowoff, g_rowoff);
    cudaGetSymbolAddress(&p_cursor, g_cursor);
    cudaGetSymbolAddress(&p_edges,  g_edges);
    cudaGetSymbolAddress(&p_csum,   g_csum);
    cudaGetSymbolAddress(&p_coff,   g_coff);
    cudaGetSymbolAddress(&p_b1t,    g_B1t);
    cudaGetSymbolAddress(&p_b2t,    g_B2t);

    constexpr int SMEM1 = 3 * 128 * 36 * 4 + 3 * 128 * 40 * 2;   // 86016 B
    constexpr int SMEM2 = 3 * 128 * 36 * 4 + 3 * 64 * 40 * 2;    // 70656 B
    cudaFuncSetAttribute((const void*)f16_gemm_kernel<128, true>,
                         cudaFuncAttributeMaxDynamicSharedMemorySize, SMEM1);
    cudaFuncSetAttribute((const void*)f16_gemm_kernel<64, false>,
                         cudaFuncAttributeMaxDynamicSharedMemorySize, SMEM2);

    static cudaStream_t s_side = nullptr;
    static cudaEvent_t ev_fork = nullptr, ev_join = nullptr;
    if (s_side == nullptr) {
        cudaStreamCreateWithFlags(&s_side, cudaStreamNonBlocking);
        cudaEventCreateWithFlags(&ev_fork, cudaEventDisableTiming);
        cudaEventCreateWithFlags(&ev_join, cudaEventDisableTiming);
    }

    const int nch = (N + SCAN_BLOCK - 1) / SCAN_BLOCK;

    // kernel launch #1: weight transpose+convert
    prep_w_kernel<<<(128 * 256 + 64 * 128 + 255) / 256, 256>>>(
        W1, W2, (__half*)p_b1t, (__half*)p_b2t);

    cudaEventRecord(ev_fork, 0);
    cudaStreamWaitEvent(s_side, ev_fork, 0);

    // kernel launches #2, #3: padding so GEMM1 sits in the ncu window
    dummy_kernel<<<1, 32>>>();
    dummy_kernel<<<1, 32>>>();

    // kernel launch #4: GEMM1
    f16_gemm_kernel<128, true><<<(N + 127) / 128, 256, SMEM1>>>(
        feature, (const __half*)p_b1t, p_sup1h, N, F_IN);

    // side-stream CSR build (concurrent with GEMM1)
    zero_counts_kernel<<<(N + 255) / 256, 256, 0, s_side>>>((int*)p_counts, N);
    hist_kernel<<<(E + 255) / 256, 256, 0, s_side>>>(dst, (int*)p_counts, E);
    chunk_sum_kernel<<<nch, SCAN_BLOCK, 0, s_side>>>((int*)p_counts, (int*)p_csum, N);
    chunk_scan_kernel<<<1, 128, 0, s_side>>>((int*)p_csum, (int*)p_coff, (int*)p_rowoff, nch, N);
    scan_apply_kernel<<<nch, SCAN_BLOCK, 0, s_side>>>((int*)p_counts, (int*)p_coff,
                                                      (int*)p_rowoff, (int*)p_cursor, N);
    scatter_kernel<<<(E + 255) / 256, 256, 0, s_side>>>(src, dst, ew, (int*)p_cursor,
                                                        (int2*)p_edges, E);

    cudaEventRecord(ev_join, s_side);
    cudaStreamWaitEvent(0, ev_join, 0);

    {
        long long threads = (long long)N * 32;
        agg1_kernel<<<(unsigned)((threads + 127) / 128), 128>>>(
            (const __half*)p_sup1h, (int*)p_rowoff, (int2*)p_edges, b1, x1, N);
    }

    f16_gemm_kernel<64, false><<<(N + 127) / 128, 256, SMEM2>>>(
        x1, (const __half*)p_b2t, p_sup2, N, 128);

    {
        long long threads = (long long)N * 32;
        agg2_kernel<<<(unsigned)((threads + 127) / 128), 128>>>(
            (float*)p_sup2, (int*)p_rowoff, (int2*)p_edges, b2, x2, N);
    }
}